// round 5
// baseline (speedup 1.0000x reference)
#include <cuda_runtime.h>
#include <math.h>
#include <cstdint>

// ---------------- problem constants ----------------
#define B_    256
#define Nn    21
#define PHs   12
#define FEAT  8
#define INP_  256
#define LAT_  64
#define HID_  512
#define OUTD  128
#define NT_   4
#define IN0_  328
#define HZ_   320
#define G3_   1536
#define BN_   (B_*Nn)

#define OFF_DQ   0
#define OFF_COV  (B_*PHs*Nn*4)
#define OFF_XT   (OFF_COV + B_*PHs*Nn*6)

// ---------------- device scratch ----------------
__device__ float g_xin[BN_*IN0_];        // tf32-rounded
__device__ float g_base[BN_*G3_];
__device__ float g_hr[BN_*G3_];
__device__ float g_tmp0[BN_*HID_];
__device__ float g_h[2][BN_*HID_];       // full precision (recurrence)
__device__ float g_hrnd[2][BN_*HID_];    // tf32-rounded (GEMM input)
__device__ float g_y[BN_*HID_];          // tf32-rounded tanh(h)
__device__ float g_pqc[BN_*256];
__device__ float g_ys[BN_*OUTD];
__device__ float g_yc[BN_*OUTD];
__device__ float g_xc[BN_*FEAT];
__device__ float g_qc[BN_*4];
__device__ float g_G0n[Nn*Nn], g_Gn[Nn*Nn], g_Gqn[Nn*Nn], g_Gcn[Nn*Nn];
// pre-rounded weights
__device__ float g_W0r[NT_*HID_*IN0_];
__device__ float g_Wihr[NT_*G3_*HZ_];
__device__ float g_Whhr[NT_*G3_*HID_];
__device__ float g_Wqc[NT_*256*HID_];
__device__ float g_bqc[Nn*256];

// ---------------- helpers ----------------
__device__ __forceinline__ float tf32r(float x) {
    float r; asm("cvt.rna.tf32.f32 %0, %1;" : "=f"(r) : "f"(x)); return r;
}
__device__ __forceinline__ uint32_t smem_u32(const void* p) {
    uint32_t a;
    asm("{ .reg .u64 t; cvta.to.shared.u64 t, %1; cvt.u32.u64 %0, t; }" : "=r"(a) : "l"(p));
    return a;
}
__device__ __forceinline__ void mma_tf32(float* d,
    uint32_t a0, uint32_t a1, uint32_t a2, uint32_t a3,
    uint32_t b0, uint32_t b1)
{
    asm volatile(
        "mma.sync.aligned.m16n8k8.row.col.f32.tf32.tf32.f32 "
        "{%0,%1,%2,%3}, {%4,%5,%6,%7}, {%8,%9}, {%0,%1,%2,%3};"
        : "+f"(d[0]), "+f"(d[1]), "+f"(d[2]), "+f"(d[3])
        : "r"(a0), "r"(a1), "r"(a2), "r"(a3), "r"(b0), "r"(b1));
}
__device__ __forceinline__ void cpa4(uint32_t dst, const float* src, int sz) {
    asm volatile("cp.async.ca.shared.global [%0], [%1], 4, %2;"
                 :: "r"(dst), "l"(src), "r"(sz) : "memory");
}
#define CP_COMMIT() asm volatile("cp.async.commit_group;" ::: "memory")
#define CP_WAIT0()  asm volatile("cp.async.wait_group 0;" ::: "memory")

// ---------------- prep kernels ----------------
__global__ void knorms(const float* __restrict__ G0, const float* __restrict__ Grnn,
                       const float* __restrict__ GA, const float* __restrict__ Gq,
                       const float* __restrict__ Gc)
{
    int i = threadIdx.x;
    if (i >= 4*Nn) return;
    int mat = i / Nn, r = i % Nn;
    const float* src = (mat==0)?G0:(mat==1)?Grnn:(mat==2)?Gq:Gc;
    float* dst = (mat==0)?g_G0n:(mat==1)?g_Gn:(mat==2)?g_Gqn:g_Gcn;
    float s = 0.f;
    for (int m = 0; m < Nn; m++) s += fabsf(src[r*Nn+m]);
    s = fmaxf(s, 1e-12f);
    for (int m = 0; m < Nn; m++) {
        float v = src[r*Nn+m] / s;
        if (mat == 1) v += GA[r*Nn+m];
        dst[r*Nn+m] = v;
    }
}

__global__ void kprep(const float* __restrict__ x, const float* __restrict__ h,
                      const float* __restrict__ z, const float* __restrict__ qt,
                      float* __restrict__ out)
{
    int idx = blockIdx.x * blockDim.x + threadIdx.x;
    if (idx < BN_*IN0_) {
        int bn = idx / IN0_, k = idx % IN0_;
        int b = bn / Nn, n = bn % Nn;
        float v;
        if (k < FEAT)            v = x[((b*2 + 0)*Nn + n)*FEAT + k];
        else if (k < FEAT+LAT_)  v = z[bn*LAT_ + (k - FEAT)];
        else                     v = h[bn*INP_ + (k - FEAT - LAT_)];
        g_xin[idx] = tf32r(v);
    }
    if (idx < BN_*FEAT) {
        int bn = idx / FEAT, f = idx % FEAT;
        int b = bn / Nn, n = bn % Nn;
        float xv = x[((b*2 + 1)*Nn + n)*FEAT + f];
        g_xc[idx] = xv;
        out[OFF_XT + idx] = xv;
    }
    if (idx < BN_*4) g_qc[idx] = qt[idx];
}

// pre-round all GEMM weights (tf32)
#define NW0  (NT_*HID_*IN0_)
#define NWIH (NT_*G3_*HZ_)
#define NWHH (NT_*G3_*HID_)
__global__ void kroundw(const float* __restrict__ W0, const float* __restrict__ Wih,
                        const float* __restrict__ Whh)
{
    int idx = blockIdx.x * blockDim.x + threadIdx.x;
    if (idx < NW0) {
        g_W0r[idx] = tf32r(W0[idx]);
    } else if (idx < NW0 + NWIH) {
        int j = idx - NW0;
        int row = j / HZ_, k = j % HZ_;
        g_Wihr[j] = tf32r(Wih[(size_t)row * IN0_ + FEAT + k]);
    } else if (idx < NW0 + NWIH + NWHH) {
        int j = idx - NW0 - NWIH;
        g_Whhr[j] = tf32r(Whh[j]);
    }
}

__global__ void kbuildwqc(const float* __restrict__ Wq, const float* __restrict__ Wc,
                          const float* __restrict__ bq, const float* __restrict__ bc)
{
    int idx = blockIdx.x * blockDim.x + threadIdx.x;
    if (idx < NT_*256*HID_) {
        int t = idx / (256*HID_);
        int r = (idx / HID_) % 256;
        int k = idx % HID_;
        float v = (r < 128) ? Wq[((size_t)t*128 + r)*HID_ + k]
                            : Wc[((size_t)t*128 + (r-128))*HID_ + k];
        g_Wqc[idx] = tf32r(v);
    }
    if (idx < Nn*256) {
        int n = idx / 256, c = idx % 256;
        g_bqc[idx] = (c < 128) ? bq[n*128 + c] : bc[n*128 + (c-128)];
    }
}

// ---------------- mma.sync tf32 GEMM, cp.async double-buffered ----------------
#define KSTR 40

__global__ void __launch_bounds__(256, 2) ktc(
    int asel, int lda, int aoff,
    int wsel, int ldw,
    int G, int K,
    const float* biasg, int csel,
    const int* __restrict__ T)
{
    extern __shared__ float smx[];
    const int STG = 128*KSTR;

    const float* A = (asel==0)?g_xin : (asel==1)?g_hrnd[0] : (asel==2)?g_hrnd[1] : g_y;
    const float* W = (wsel==0)?g_W0r : (wsel==1)?g_Wihr : (wsel==2)?g_Whhr : g_Wqc;
    const float* bias = biasg ? biasg : g_bqc;
    float* C = (csel==0)?g_tmp0 : (csel==1)?g_base : (csel==2)?g_hr : g_pqc;

    int n  = blockIdx.z;
    int t  = T[n];
    int b0 = blockIdx.x * 128;
    int g0 = blockIdx.y * 128;
    int tid  = threadIdx.x;
    int wid  = tid >> 5, lane = tid & 31;
    int wm = wid >> 1, wn = wid & 1;
    int gq = lane >> 2, tg = lane & 3;

    const size_t strideA = (size_t)Nn * lda;
    const float* An = A + ((size_t)b0 * Nn + n) * lda + aoff;
    const float* Wt = W + ((size_t)t * G + g0) * ldw;

    int sr = tid >> 3;
    int sq = tid & 7;
    int sp = ((sq >> 1) << 3) | (sq & 1);

    const float* gA = An + (size_t)sr * strideA + sq*4;
    const float* gB = Wt + (size_t)sr * ldw + sq*4;
    uint32_t sA0 = smem_u32(smx) + (sr*KSTR + sp)*4;
    uint32_t sB0 = sA0 + 2*STG*4;

    float acc[2][8][4];
    #pragma unroll
    for (int a = 0; a < 2; a++)
        #pragma unroll
        for (int b = 0; b < 8; b++)
            #pragma unroll
            for (int c = 0; c < 4; c++) acc[a][b][c] = 0.f;

    int ntiles = (K + 31) / 32;

    auto issue = [&](int kt, int buf) {
        int k0 = kt * 32;
        int kbase = k0 + sq*4;
        uint32_t da = sA0 + buf*STG*4;
        uint32_t db = sB0 + buf*STG*4;
        #pragma unroll
        for (int i = 0; i < 4; i++) {
            const float* pa = gA + (size_t)i*32*strideA + k0;
            const float* pb = gB + (size_t)i*32*ldw + k0;
            uint32_t oa = da + i*32*KSTR*4;
            uint32_t ob = db + i*32*KSTR*4;
            #pragma unroll
            for (int j = 0; j < 4; j++) {
                int sz = (kbase + j < K) ? 4 : 0;
                const float* spa = sz ? (pa + j) : An;
                const float* spb = sz ? (pb + j) : Wt;
                cpa4(oa + j*8, spa, sz);
                cpa4(ob + j*8, spb, sz);
            }
        }
    };

    issue(0, 0); CP_COMMIT();

    for (int kt = 0; kt < ntiles; kt++) {
        CP_WAIT0();
        __syncthreads();
        if (kt + 1 < ntiles) { issue(kt + 1, (kt + 1) & 1); CP_COMMIT(); }

        const float* AsB = smx + (kt & 1)*STG;
        const float* BsB = smx + 2*STG + (kt & 1)*STG;
        #pragma unroll
        for (int s = 0; s < 4; s++) {
            int p0 = s * 8 + tg * 2;
            float2 alo[2], ahi[2];
            #pragma unroll
            for (int mt = 0; mt < 2; mt++) {
                int row = wm * 32 + mt * 16 + gq;
                alo[mt] = *(const float2*)(AsB + row * KSTR + p0);
                ahi[mt] = *(const float2*)(AsB + (row + 8) * KSTR + p0);
            }
            #pragma unroll
            for (int nt = 0; nt < 8; nt++) {
                int col = wn * 64 + nt * 8 + gq;
                float2 bf = *(const float2*)(BsB + col * KSTR + p0);
                uint32_t bb0 = __float_as_uint(bf.x), bb1 = __float_as_uint(bf.y);
                #pragma unroll
                for (int mt = 0; mt < 2; mt++) {
                    mma_tf32(acc[mt][nt],
                             __float_as_uint(alo[mt].x), __float_as_uint(ahi[mt].x),
                             __float_as_uint(alo[mt].y), __float_as_uint(ahi[mt].y),
                             bb0, bb1);
                }
            }
        }
    }

    const float* bp = bias + (size_t)n * G + g0;
    #pragma unroll
    for (int mt = 0; mt < 2; mt++) {
        int row = b0 + wm * 32 + mt * 16 + gq;
        float* C0 = C + ((size_t)row * Nn + n) * G + g0;
        float* C1 = C + ((size_t)(row + 8) * Nn + n) * G + g0;
        #pragma unroll
        for (int nt = 0; nt < 8; nt++) {
            int col = wn * 64 + nt * 8 + tg * 2;
            float2 o0, o1;
            o0.x = acc[mt][nt][0] + bp[col];
            o0.y = acc[mt][nt][1] + bp[col + 1];
            o1.x = acc[mt][nt][2] + bp[col];
            o1.y = acc[mt][nt][3] + bp[col + 1];
            *(float2*)(C0 + col) = o0;
            *(float2*)(C1 + col) = o1;
        }
    }
}

// ---------------- rnn_h init mix ----------------
__global__ void kmix_rnnh()
{
    int b = blockIdx.x, c0 = blockIdx.y * 64;
    __shared__ float sh[Nn][64];
    __shared__ float sG[Nn*Nn];
    int tid = threadIdx.x;
    for (int i = tid; i < Nn*Nn; i += 256) sG[i] = g_G0n[i];
    for (int i = tid; i < Nn*64; i += 256) {
        int m = i >> 6, c = i & 63;
        sh[m][c] = g_tmp0[((size_t)(b*Nn) + m) * HID_ + c0 + c];
    }
    __syncthreads();
    for (int i = tid; i < Nn*64; i += 256) {
        int n = i >> 6, c = i & 63;
        float s = 0.f;
        #pragma unroll
        for (int m = 0; m < Nn; m++) s += sG[n*Nn+m] * sh[m][c];
        size_t hidx = ((size_t)(b*Nn) + n) * HID_ + c0 + c;
        g_h[0][hidx] = s;
        g_hrnd[0][hidx] = tf32r(s);
    }
}

// ---------------- per-step: graph mix + GRU gates ----------------
// dynamic smem layout (floats); SXW must be 16B-aligned (float4 access)
#define KG_SX   0
#define KG_SHH  (3*Nn*64)                       // 4032
#define KG_SG   (2*3*Nn*64)                     // 8064
#define KG_SXW  ((KG_SG + Nn*Nn + 3) & ~3)      // 8508 (16B aligned)
#define KG_SXC  (KG_SXW + 4*3*64*8)
#define KG_TOT  (KG_SXC + Nn*8)

__global__ void kgates(const float* __restrict__ Wih, const int* __restrict__ T, int cur)
{
    extern __shared__ float sm[];
    __shared__ int sT[Nn];
    int b = blockIdx.x, c0 = blockIdx.y * 64;
    int tid = threadIdx.x;

    float* sx  = sm + KG_SX;
    float* shh = sm + KG_SHH;
    float* sG  = sm + KG_SG;
    float* sxw = sm + KG_SXW;
    float* sxc = sm + KG_SXC;

    if (tid < Nn) sT[tid] = T[tid];
    for (int i = tid; i < Nn*Nn; i += 256) sG[i] = g_Gn[i];
    for (int i = tid; i < Nn*8; i += 256) sxc[i] = g_xc[(size_t)b*Nn*FEAT + i];
    for (int i = tid; i < 4*3*64*2; i += 256) {
        int q4 = i & 1;
        int c  = (i >> 1) & 63;
        int s  = (i >> 7) % 3;
        int t  = i / (2*64*3);
        int g  = s*HID_ + c0 + c;
        float4 v = *(const float4*)(Wih + ((size_t)t * G3_ + g) * IN0_ + q4*4);
        *(float4*)(sxw + (((t*3 + s)*64 + c)*8) + q4*4) = v;
    }
    __syncthreads();

    for (int i = tid; i < 3*Nn*64; i += 256) {
        int s = i / (Nn*64), rem = i % (Nn*64);
        int m = rem >> 6, c = rem & 63;
        int g = s*HID_ + c0 + c;
        int t = sT[m];
        const float* wx = sxw + ((t*3 + s)*64 + c)*8;
        const float* xc = sxc + m*8;
        float acc = g_base[((size_t)(b*Nn) + m) * G3_ + g];
        #pragma unroll
        for (int q = 0; q < FEAT; q++) acc += xc[q] * wx[q];
        sx[(s*Nn + m)*64 + c]  = acc;
        shh[(s*Nn + m)*64 + c] = g_hr[((size_t)(b*Nn) + m) * G3_ + g];
    }
    __syncthreads();
    for (int i = tid; i < Nn*64; i += 256) {
        int n = i >> 6, c = i & 63;
        float ir=0,iz=0,ic=0,hr_=0,hz2=0,hc2=0;
        #pragma unroll
        for (int m = 0; m < Nn; m++) {
            float gw = sG[n*Nn+m];
            ir  += gw*sx[(0*Nn+m)*64+c];  iz  += gw*sx[(1*Nn+m)*64+c];  ic  += gw*sx[(2*Nn+m)*64+c];
            hr_ += gw*shh[(0*Nn+m)*64+c]; hz2 += gw*shh[(1*Nn+m)*64+c]; hc2 += gw*shh[(2*Nn+m)*64+c];
        }
        float r  = 1.f / (1.f + expf(-(ir + hr_)));
        float zg = 1.f / (1.f + expf(-(iz + hz2)));
        float nn = tanhf(ic + r*hc2);
        size_t hidx = ((size_t)(b*Nn) + n) * HID_ + c0 + c;
        float hc = g_h[cur][hidx];
        float hnew = (1.f - zg)*nn + zg*hc;
        g_h[cur^1][hidx] = hnew;
        g_hrnd[cur^1][hidx] = tf32r(hnew);
        g_y[hidx] = tf32r(tanhf(hnew));
    }
}

// ---------------- per-step: output mixes ----------------
__global__ void kmixout()
{
    int b = blockIdx.x;
    __shared__ float sq[Nn][OUTD];
    __shared__ float sc[Nn][OUTD];
    __shared__ float sGq[Nn*Nn], sGc[Nn*Nn];
    int tid = threadIdx.x;
    for (int i = tid; i < Nn*Nn; i += 256) { sGq[i] = g_Gqn[i]; sGc[i] = g_Gcn[i]; }
    for (int i = tid; i < Nn*OUTD; i += 256) {
        int m = i >> 7, c = i & 127;
        sq[m][c] = g_pqc[((size_t)(b*Nn) + m) * 256 + c];
        sc[m][c] = g_pqc[((size_t)(b*Nn) + m) * 256 + 128 + c];
    }
    __syncthreads();
    for (int i = tid; i < Nn*OUTD; i += 256) {
        int n = i >> 7, c = i & 127;
        float s1 = 0.f, s2 = 0.f;
        #pragma unroll
        for (int m = 0; m < Nn; m++) {
            s1 += sGq[n*Nn+m] * sq[m][c];
            s2 += sGc[n*Nn+m] * sc[m][c];
        }
        size_t o = ((size_t)(b*Nn) + n) * OUTD + c;
        g_ys[o] = tanhf(s1);
        g_yc[o] = tanhf(s2);
    }
}

// ---------------- per-step: heads + quaternion ----------------
__global__ void khead(const float* __restrict__ W3, const float* __restrict__ b3,
                      const float* __restrict__ W6, const float* __restrict__ b6,
                      const int* __restrict__ T, float* __restrict__ out, int step)
{
    int wid  = (blockIdx.x * blockDim.x + threadIdx.x) >> 5;
    int lane = threadIdx.x & 31;
    if (wid >= BN_) return;
    int b = wid / Nn, n = wid % Nn;
    int t = T[n];
    float val = 0.f;
    if (lane < 3) {
        const float* ys = g_ys + (size_t)wid * OUTD;
        const float* w  = W3 + ((size_t)t*3 + lane) * OUTD;
        #pragma unroll 8
        for (int k = 0; k < OUTD; k++) val += ys[k] * w[k];
        val += b3[n*3 + lane];
    } else if (lane < 9) {
        int a = lane - 3;
        const float* yc = g_yc + (size_t)wid * OUTD;
        const float* w  = W6 + ((size_t)t*6 + a) * OUTD;
        #pragma unroll 8
        for (int k = 0; k < OUTD; k++) val += yc[k] * w[k];
        val += b6[n*6 + a];
    }
    unsigned mask = 0xffffffffu;
    float v0 = __shfl_sync(mask, val, 0);
    float v1 = __shfl_sync(mask, val, 1);
    float v2 = __shfl_sync(mask, val, 2);
    float c0 = __shfl_sync(mask, val, 3);
    float c1 = __shfl_sync(mask, val, 4);
    float c2 = __shfl_sync(mask, val, 5);
    float c3 = __shfl_sync(mask, val, 6);
    float c4 = __shfl_sync(mask, val, 7);
    float c5 = __shfl_sync(mask, val, 8);
    if (lane == 0) {
        float theta = sqrtf(v0*v0 + v1*v1 + v2*v2);
        float w1 = cosf(0.5f * theta);
        float kk = (theta > 1e-8f) ? (sinf(0.5f*theta) / fmaxf(theta, 1e-8f)) : 0.5f;
        float dq0 = w1, dq1 = kk*v0, dq2 = kk*v1, dq3 = kk*v2;
        float* qc = g_qc + (size_t)wid * 4;
        float qw = qc[0], qx = qc[1], qy = qc[2], qz = qc[3];
        float nw = dq0*qw - (dq1*qx + dq2*qy + dq3*qz);
        float nx = dq0*qx + qw*dq1 + (dq2*qz - dq3*qy);
        float ny = dq0*qy + qw*dq2 + (dq3*qx - dq1*qz);
        float nz = dq0*qz + qw*dq3 + (dq1*qy - dq2*qx);
        qc[0]=nw; qc[1]=nx; qc[2]=ny; qc[3]=nz;
        float* xc = g_xc + (size_t)wid * FEAT;
        xc[0]=nw; xc[1]=nx; xc[2]=ny; xc[3]=nz;
        xc[4]=dq0; xc[5]=dq1; xc[6]=dq2; xc[7]=dq3;
        size_t od = ((size_t)b * PHs + step) * Nn + n;
        out[OFF_DQ  + od*4 + 0] = dq0; out[OFF_DQ + od*4 + 1] = dq1;
        out[OFF_DQ  + od*4 + 2] = dq2; out[OFF_DQ + od*4 + 3] = dq3;
        out[OFF_COV + od*6 + 0] = c0;  out[OFF_COV + od*6 + 1] = c1;
        out[OFF_COV + od*6 + 2] = c2;  out[OFF_COV + od*6 + 3] = c3;
        out[OFF_COV + od*6 + 4] = c4;  out[OFF_COV + od*6 + 5] = c5;
    }
}

// ---------------- launch ----------------
extern "C" void kernel_launch(void* const* d_in, const int* in_sizes, int n_in,
                              void* d_out, int out_size)
{
    const float* x    = (const float*)d_in[0];
    const float* h    = (const float*)d_in[1];
    const float* z    = (const float*)d_in[2];
    const float* q_t  = (const float*)d_in[3];
    const int*   T    = (const int*)  d_in[4];
    const float* W0   = (const float*)d_in[6];
    const float* b0p  = (const float*)d_in[7];
    const float* G0   = (const float*)d_in[8];
    const float* Wih  = (const float*)d_in[9];
    const float* Whh  = (const float*)d_in[10];
    const float* bih  = (const float*)d_in[11];
    const float* bhh  = (const float*)d_in[12];
    const float* Grnn = (const float*)d_in[13];
    const float* GA   = (const float*)d_in[14];
    const float* Wq   = (const float*)d_in[15];
    const float* bq   = (const float*)d_in[16];
    const float* Gq   = (const float*)d_in[17];
    const float* Wc   = (const float*)d_in[18];
    const float* bc   = (const float*)d_in[19];
    const float* Gc   = (const float*)d_in[20];
    const float* W3   = (const float*)d_in[21];
    const float* b3   = (const float*)d_in[22];
    const float* W6   = (const float*)d_in[23];
    const float* b6   = (const float*)d_in[24];
    float* out = (float*)d_out;

    const int SM_KTC = 4 * 128 * KSTR * 4;
    const int SM_KG  = KG_TOT * 4;
    static int attr_done = 0;
    if (!attr_done) {
        cudaFuncSetAttribute(ktc, cudaFuncAttributeMaxDynamicSharedMemorySize, SM_KTC);
        cudaFuncSetAttribute(kgates, cudaFuncAttributeMaxDynamicSharedMemorySize, SM_KG);
        attr_done = 1;
    }

    knorms<<<1, 128>>>(G0, Grnn, GA, Gq, Gc);
    kprep<<<(BN_*IN0_ + 255)/256, 256>>>(x, h, z, q_t, out);
    kroundw<<<(NW0 + NWIH + NWHH + 255)/256, 256>>>(W0, Wih, Whh);
    kbuildwqc<<<(NT_*256*HID_ + 255)/256, 256>>>(Wq, Wc, bq, bc);

    // tmp0 = xin(328) @ W0^T + b0
    ktc<<<dim3(2, HID_/128, Nn), 256, SM_KTC>>>(0, IN0_, 0, 0, IN0_, HID_, IN0_, b0p, 0, T);
    kmix_rnnh<<<dim3(B_, HID_/64), 256>>>();

    // base = h_z(320) @ Wih_hz^T + bih
    ktc<<<dim3(2, G3_/128, Nn), 256, SM_KTC>>>(0, IN0_, FEAT, 1, HZ_, G3_, HZ_, bih, 1, T);

    for (int t = 0; t < PHs; t++) {
        int cur = t & 1;
        // hr = h @ Whh^T + bhh
        ktc<<<dim3(2, G3_/128, Nn), 256, SM_KTC>>>(1 + cur, HID_, 0, 2, HID_, G3_, HID_, bhh, 2, T);
        kgates<<<dim3(B_, HID_/64), 256, SM_KG>>>(Wih, T, cur);
        // [pq|pc] = y @ [Wq;Wc]^T + [bq;bc]
        ktc<<<dim3(2, 2, Nn), 256, SM_KTC>>>(3, HID_, 0, 3, HID_, 256, HID_, nullptr, 3, T);
        kmixout<<<B_, 256>>>();
        khead<<<(BN_*32 + 255)/256, 256>>>(W3, b3, W6, b6, T, out, t);
    }
}

// round 6
// speedup vs baseline: 1.1189x; 1.1189x over previous
#include <cuda_runtime.h>
#include <math.h>
#include <cstdint>

#define B_    256
#define Nn    21
#define PHs   12
#define FEAT  8
#define INP_  256
#define LAT_  64
#define HID_  512
#define OUTD  128
#define NT_   4
#define IN0_  328
#define HZ_   320
#define G3_   1536
#define BN_   (B_*Nn)

#define OFF_DQ   0
#define OFF_COV  (B_*PHs*Nn*4)
#define OFF_XT   (OFF_COV + B_*PHs*Nn*6)

__host__ __device__ __forceinline__ int kperm(int k) {
    return (k & ~7) | ((k & 3) << 1) | ((k >> 2) & 1);
}

__device__ float g_xin[BN_*IN0_];
__device__ float g_base[BN_*G3_];
__device__ float g_hr[BN_*G3_];
__device__ float g_tmp0[BN_*HID_];
__device__ float g_h[2][BN_*HID_];
__device__ float g_hrnd[2][BN_*HID_];
__device__ float g_y[BN_*HID_];
__device__ float g_pqc[BN_*256];
__device__ float g_xc[BN_*FEAT];
__device__ float g_qc[BN_*4];
__device__ float g_G0n[Nn*Nn], g_Gn[Nn*Nn], g_Gqn[Nn*Nn], g_Gcn[Nn*Nn];
__device__ float g_W0r[NT_*HID_*IN0_];
__device__ float g_Wihr[NT_*G3_*HZ_];
__device__ float g_Whhr[NT_*G3_*HID_];
__device__ float g_Wqc[NT_*256*HID_];
__device__ float g_bqc[Nn*256];

__device__ __forceinline__ float tf32r(float x) {
    float r; asm("cvt.rna.tf32.f32 %0, %1;" : "=f"(r) : "f"(x)); return r;
}
__device__ __forceinline__ uint32_t smem_u32(const void* p) {
    uint32_t a;
    asm("{ .reg .u64 t; cvta.to.shared.u64 t, %1; cvt.u32.u64 %0, t; }" : "=r"(a) : "l"(p));
    return a;
}
__device__ __forceinline__ void mma_tf32(float* d,
    uint32_t a0, uint32_t a1, uint32_t a2, uint32_t a3,
    uint32_t b0, uint32_t b1)
{
    asm volatile(
        "mma.sync.aligned.m16n8k8.row.col.f32.tf32.tf32.f32 "
        "{%0,%1,%2,%3}, {%4,%5,%6,%7}, {%8,%9}, {%0,%1,%2,%3};"
        : "+f"(d[0]), "+f"(d[1]), "+f"(d[2]), "+f"(d[3])
        : "r"(a0), "r"(a1), "r"(a2), "r"(a3), "r"(b0), "r"(b1));
}
__device__ __forceinline__ void cpa16(uint32_t dst, const float* src, int sz) {
    asm volatile("cp.async.cg.shared.global [%0], [%1], 16, %2;"
                 :: "r"(dst), "l"(src), "r"(sz) : "memory");
}
#define CP_COMMIT() asm volatile("cp.async.commit_group;" ::: "memory")
#define CP_WAIT0()  asm volatile("cp.async.wait_group 0;" ::: "memory")

__global__ void knorms(const float* __restrict__ G0, const float* __restrict__ Grnn,
                       const float* __restrict__ GA, const float* __restrict__ Gq,
                       const float* __restrict__ Gc)
{
    int i = threadIdx.x;
    if (i >= 4*Nn) return;
    int mat = i / Nn, r = i % Nn;
    const float* src = (mat==0)?G0:(mat==1)?Grnn:(mat==2)?Gq:Gc;
    float* dst = (mat==0)?g_G0n:(mat==1)?g_Gn:(mat==2)?g_Gqn:g_Gcn;
    float s = 0.f;
    for (int m = 0; m < Nn; m++) s += fabsf(src[r*Nn+m]);
    s = fmaxf(s, 1e-12f);
    for (int m = 0; m < Nn; m++) {
        float v = src[r*Nn+m] / s;
        if (mat == 1) v += GA[r*Nn+m];
        dst[r*Nn+m] = v;
    }
}

__global__ void kprep(const float* __restrict__ x, const float* __restrict__ h,
                      const float* __restrict__ z, const float* __restrict__ qt,
                      float* __restrict__ out)
{
    int idx = blockIdx.x * blockDim.x + threadIdx.x;
    if (idx < BN_*IN0_) {
        int bn = idx / IN0_, k = idx % IN0_;
        int b = bn / Nn, n = bn % Nn;
        float v;
        if (k < FEAT)            v = x[((b*2 + 0)*Nn + n)*FEAT + k];
        else if (k < FEAT+LAT_)  v = z[bn*LAT_ + (k - FEAT)];
        else                     v = h[bn*INP_ + (k - FEAT - LAT_)];
        g_xin[bn*IN0_ + kperm(k)] = tf32r(v);
    }
    if (idx < BN_*FEAT) {
        int bn = idx / FEAT, f = idx % FEAT;
        int b = bn / Nn, n = bn % Nn;
        float xv = x[((b*2 + 1)*Nn + n)*FEAT + f];
        g_xc[idx] = xv;
        out[OFF_XT + idx] = xv;
    }
    if (idx < BN_*4) g_qc[idx] = qt[idx];
}

#define NW0  (NT_*HID_*IN0_)
#define NWIH (NT_*G3_*HZ_)
#define NWHH (NT_*G3_*HID_)
__global__ void kroundw(const float* __restrict__ W0, const float* __restrict__ Wih,
                        const float* __restrict__ Whh)
{
    int idx = blockIdx.x * blockDim.x + threadIdx.x;
    if (idx < NW0) {
        int row = idx / IN0_, k = idx % IN0_;
        g_W0r[(size_t)row*IN0_ + kperm(k)] = tf32r(W0[idx]);
    } else if (idx < NW0 + NWIH) {
        int j = idx - NW0;
        int row = j / HZ_, k = j % HZ_;
        g_Wihr[(size_t)row*HZ_ + kperm(k)] = tf32r(Wih[(size_t)row * IN0_ + FEAT + k]);
    } else if (idx < NW0 + NWIH + NWHH) {
        int j = idx - NW0 - NWIH;
        int row = j / HID_, k = j % HID_;
        g_Whhr[(size_t)row*HID_ + kperm(k)] = tf32r(Whh[j]);
    }
}

__global__ void kbuildwqc(const float* __restrict__ Wq, const float* __restrict__ Wc,
                          const float* __restrict__ bq, const float* __restrict__ bc)
{
    int idx = blockIdx.x * blockDim.x + threadIdx.x;
    if (idx < NT_*256*HID_) {
        int t = idx / (256*HID_);
        int r = (idx / HID_) % 256;
        int k = idx % HID_;
        float v = (r < 128) ? Wq[((size_t)t*128 + r)*HID_ + k]
                            : Wc[((size_t)t*128 + (r-128))*HID_ + k];
        g_Wqc[((size_t)t*256 + r)*HID_ + kperm(k)] = tf32r(v);
    }
    if (idx < Nn*256) {
        int n = idx / 256, c = idx % 256;
        g_bqc[idx] = (c < 128) ? bq[n*128 + c] : bc[n*128 + (c-128)];
    }
}

#define KSTR 40

__global__ void __launch_bounds__(256, 2) ktc(
    int asel, int lda, int wsel, int ldw,
    int G, int K,
    const float* biasg, int csel,
    const int* __restrict__ T)
{
    extern __shared__ float smx[];
    const int STG = 128*KSTR;

    const float* A = (asel==0)?g_xin : (asel==1)?g_hrnd[0] : (asel==2)?g_hrnd[1]
                   : (asel==3)?g_y : (g_xin + FEAT);
    const float* W = (wsel==0)?g_W0r : (wsel==1)?g_Wihr : (wsel==2)?g_Whhr : g_Wqc;
    const float* bias = biasg ? biasg : g_bqc;
    float* C = (csel==0)?g_tmp0 : (csel==1)?g_base : (csel==2)?g_hr : g_pqc;

    int n  = blockIdx.z;
    int t  = T[n];
    int b0 = blockIdx.x * 128;
    int g0 = blockIdx.y * 128;
    int tid  = threadIdx.x;
    int wid  = tid >> 5, lane = tid & 31;
    int wm = wid >> 1, wn = wid & 1;
    int gq = lane >> 2, tg = lane & 3;

    const size_t strideA = (size_t)Nn * lda;
    const float* An = A + ((size_t)b0 * Nn + n) * lda;
    const float* Wt = W + ((size_t)t * G + g0) * ldw;

    int sr = tid >> 3;
    int sq = tid & 7;

    const float* gA = An + (size_t)sr * strideA + sq*4;
    const float* gB = Wt + (size_t)sr * ldw + sq*4;
    uint32_t sA0 = smem_u32(smx) + (sr*KSTR + sq*4)*4;
    uint32_t sB0 = sA0 + 2*STG*4;

    float acc[2][8][4];
    #pragma unroll
    for (int a = 0; a < 2; a++)
        #pragma unroll
        for (int b = 0; b < 8; b++)
            #pragma unroll
            for (int c = 0; c < 4; c++) acc[a][b][c] = 0.f;

    int ntiles = (K + 31) / 32;

    auto issue = [&](int kt, int buf) {
        int k0 = kt * 32;
        int sz = (k0 + sq*4 + 4 <= K) ? 16 : 0;
        const float* pa = sz ? (gA + k0) : An;
        const float* pb = sz ? (gB + k0) : Wt;
        uint32_t da = sA0 + buf*STG*4;
        uint32_t db = sB0 + buf*STG*4;
        #pragma unroll
        for (int i = 0; i < 4; i++) {
            cpa16(da + i*32*KSTR*4, pa + (size_t)i*32*strideA, sz);
            cpa16(db + i*32*KSTR*4, pb + (size_t)i*32*ldw, sz);
        }
    };

    issue(0, 0); CP_COMMIT();

    for (int kt = 0; kt < ntiles; kt++) {
        CP_WAIT0();
        __syncthreads();
        if (kt + 1 < ntiles) { issue(kt + 1, (kt + 1) & 1); CP_COMMIT(); }

        const float* AsB = smx + (kt & 1)*STG;
        const float* BsB = smx + 2*STG + (kt & 1)*STG;
        #pragma unroll
        for (int s = 0; s < 4; s++) {
            int p0 = s * 8 + tg * 2;
            float2 alo[2], ahi[2];
            #pragma unroll
            for (int mt = 0; mt < 2; mt++) {
                int row = wm * 32 + mt * 16 + gq;
                alo[mt] = *(const float2*)(AsB + row * KSTR + p0);
                ahi[mt] = *(const float2*)(AsB + (row + 8) * KSTR + p0);
            }
            #pragma unroll
            for (int nt = 0; nt < 8; nt++) {
                int col = wn * 64 + nt * 8 + gq;
                float2 bf = *(const float2*)(BsB + col * KSTR + p0);
                uint32_t bb0 = __float_as_uint(bf.x), bb1 = __float_as_uint(bf.y);
                #pragma unroll
                for (int mt = 0; mt < 2; mt++) {
                    mma_tf32(acc[mt][nt],
                             __float_as_uint(alo[mt].x), __float_as_uint(ahi[mt].x),
                             __float_as_uint(alo[mt].y), __float_as_uint(ahi[mt].y),
                             bb0, bb1);
                }
            }
        }
    }

    const float* bp = bias + (size_t)n * G + g0;
    #pragma unroll
    for (int mt = 0; mt < 2; mt++) {
        int row = b0 + wm * 32 + mt * 16 + gq;
        float* C0 = C + ((size_t)row * Nn + n) * G + g0;
        float* C1 = C + ((size_t)(row + 8) * Nn + n) * G + g0;
        #pragma unroll
        for (int nt = 0; nt < 8; nt++) {
            int col = wn * 64 + nt * 8 + tg * 2;
            float2 o0, o1;
            o0.x = acc[mt][nt][0] + bp[col];
            o0.y = acc[mt][nt][1] + bp[col + 1];
            o1.x = acc[mt][nt][2] + bp[col];
            o1.y = acc[mt][nt][3] + bp[col + 1];
            *(float2*)(C0 + col) = o0;
            *(float2*)(C1 + col) = o1;
        }
    }
}

__global__ void kmix_rnnh()
{
    int b = blockIdx.x, c0 = blockIdx.y * 64;
    __shared__ float sh[Nn][64];
    __shared__ float sG[Nn*Nn];
    int tid = threadIdx.x;
    for (int i = tid; i < Nn*Nn; i += 256) sG[i] = g_G0n[i];
    for (int i = tid; i < Nn*64; i += 256) {
        int m = i >> 6, c = i & 63;
        sh[m][c] = g_tmp0[((size_t)(b*Nn) + m) * HID_ + c0 + c];
    }
    __syncthreads();
    for (int i = tid; i < Nn*64; i += 256) {
        int n = i >> 6, c = i & 63;
        float s = 0.f;
        #pragma unroll
        for (int m = 0; m < Nn; m++) s += sG[n*Nn+m] * sh[m][c];
        size_t base = ((size_t)(b*Nn) + n) * HID_ + c0;
        g_h[0][base + c] = s;
        g_hrnd[0][base + kperm(c)] = tf32r(s);
    }
}

#define KG_SX   0
#define KG_SHH  (3*Nn*64)
#define KG_SG   (2*3*Nn*64)
#define KG_SXW  ((KG_SG + Nn*Nn + 3) & ~3)
#define KG_SXC  (KG_SXW + 4*3*64*8)
#define KG_TOT  (KG_SXC + Nn*8)

__global__ void kgates(const float* __restrict__ Wih, const int* __restrict__ T, int cur)
{
    extern __shared__ float sm[];
    __shared__ int sT[Nn];
    int b = blockIdx.x, c0 = blockIdx.y * 64;
    int tid = threadIdx.x;

    float* sx  = sm + KG_SX;
    float* shh = sm + KG_SHH;
    float* sG  = sm + KG_SG;
    float* sxw = sm + KG_SXW;
    float* sxc = sm + KG_SXC;

    if (tid < Nn) sT[tid] = T[tid];
    for (int i = tid; i < Nn*Nn; i += 256) sG[i] = g_Gn[i];
    for (int i = tid; i < Nn*8; i += 256) sxc[i] = g_xc[(size_t)b*Nn*FEAT + i];
    for (int i = tid; i < 4*3*64*2; i += 256) {
        int q4 = i & 1;
        int c  = (i >> 1) & 63;
        int s  = (i >> 7) % 3;
        int t  = i / (2*64*3);
        int g  = s*HID_ + c0 + c;
        float4 v = *(const float4*)(Wih + ((size_t)t * G3_ + g) * IN0_ + q4*4);
        *(float4*)(sxw + (((t*3 + s)*64 + c)*8) + q4*4) = v;
    }
    __syncthreads();

    for (int i = tid; i < 3*Nn*64; i += 256) {
        int s = i / (Nn*64), rem = i % (Nn*64);
        int m = rem >> 6, c = rem & 63;
        int g = s*HID_ + c0 + c;
        int t = sT[m];
        const float* wx = sxw + ((t*3 + s)*64 + c)*8;
        const float* xc = sxc + m*8;
        float acc = g_base[((size_t)(b*Nn) + m) * G3_ + g];
        #pragma unroll
        for (int q = 0; q < FEAT; q++) acc += xc[q] * wx[q];
        sx[(s*Nn + m)*64 + c]  = acc;
        shh[(s*Nn + m)*64 + c] = g_hr[((size_t)(b*Nn) + m) * G3_ + g];
    }
    __syncthreads();
    for (int i = tid; i < Nn*64; i += 256) {
        int n = i >> 6, c = i & 63;
        float ir=0,iz=0,ic=0,hr_=0,hz2=0,hc2=0;
        #pragma unroll
        for (int m = 0; m < Nn; m++) {
            float gw = sG[n*Nn+m];
            ir  += gw*sx[(0*Nn+m)*64+c];  iz  += gw*sx[(1*Nn+m)*64+c];  ic  += gw*sx[(2*Nn+m)*64+c];
            hr_ += gw*shh[(0*Nn+m)*64+c]; hz2 += gw*shh[(1*Nn+m)*64+c]; hc2 += gw*shh[(2*Nn+m)*64+c];
        }
        float r  = 1.f / (1.f + expf(-(ir + hr_)));
        float zg = 1.f / (1.f + expf(-(iz + hz2)));
        float nn = tanhf(ic + r*hc2);
        size_t base = ((size_t)(b*Nn) + n) * HID_ + c0;
        float hc = g_h[cur][base + c];
        float hnew = (1.f - zg)*nn + zg*hc;
        g_h[cur^1][base + c] = hnew;
        int cp = kperm(c);
        g_hrnd[cur^1][base + cp] = tf32r(hnew);
        g_y[base + cp] = tf32r(tanhf(hnew));
    }
}

__global__ void __launch_bounds__(256) kheadmix(
    const float* __restrict__ W3, const float* __restrict__ b3,
    const float* __restrict__ W6, const float* __restrict__ b6,
    const int* __restrict__ T, float* __restrict__ out, int step)
{
    __shared__ float sq[Nn*OUTD];
    __shared__ float sc[Nn*OUTD];
    __shared__ float sy[Nn*OUTD];
    __shared__ float syc[Nn*OUTD];
    __shared__ float sGq[Nn*Nn], sGc[Nn*Nn];
    __shared__ int sT[Nn];

    int b = blockIdx.x;
    int tid = threadIdx.x;
    if (tid < Nn) sT[tid] = T[tid];
    for (int i = tid; i < Nn*Nn; i += 256) { sGq[i] = g_Gqn[i]; sGc[i] = g_Gcn[i]; }
    for (int i = tid; i < Nn*OUTD; i += 256) {
        int m = i >> 7, c = i & 127;
        sq[i] = g_pqc[((size_t)(b*Nn) + m) * 256 + c];
        sc[i] = g_pqc[((size_t)(b*Nn) + m) * 256 + 128 + c];
    }
    __syncthreads();
    for (int i = tid; i < Nn*OUTD; i += 256) {
        int n = i >> 7, c = i & 127;
        float s1 = 0.f, s2 = 0.f;
        #pragma unroll
        for (int m = 0; m < Nn; m++) {
            s1 += sGq[n*Nn+m] * sq[m*OUTD+c];
            s2 += sGc[n*Nn+m] * sc[m*OUTD+c];
        }
        sy[i]  = tanhf(s1);
        syc[i] = tanhf(s2);
    }
    __syncthreads();

    int wid = tid >> 5, lane = tid & 31;
    for (int n = wid; n < Nn; n += 8) {
        int t = sT[n];
        float val = 0.f;
        if (lane < 3) {
            const float* ys = sy + n*OUTD;
            const float* w  = W3 + ((size_t)t*3 + lane) * OUTD;
            #pragma unroll 8
            for (int k = 0; k < OUTD; k++) val += ys[k] * w[k];
            val += b3[n*3 + lane];
        } else if (lane < 9) {
            int a = lane - 3;
            const float* yc = syc + n*OUTD;
            const float* w  = W6 + ((size_t)t*6 + a) * OUTD;
            #pragma unroll 8
            for (int k = 0; k < OUTD; k++) val += yc[k] * w[k];
            val += b6[n*6 + a];
        }
        unsigned mask = 0xffffffffu;
        float v0 = __shfl_sync(mask, val, 0);
        float v1 = __shfl_sync(mask, val, 1);
        float v2 = __shfl_sync(mask, val, 2);
        float c0 = __shfl_sync(mask, val, 3);
        float c1 = __shfl_sync(mask, val, 4);
        float c2 = __shfl_sync(mask, val, 5);
        float c3 = __shfl_sync(mask, val, 6);
        float c4 = __shfl_sync(mask, val, 7);
        float c5 = __shfl_sync(mask, val, 8);
        if (lane == 0) {
            int bn = b*Nn + n;
            float theta = sqrtf(v0*v0 + v1*v1 + v2*v2);
            float w1 = cosf(0.5f * theta);
            float kk = (theta > 1e-8f) ? (sinf(0.5f*theta) / fmaxf(theta, 1e-8f)) : 0.5f;
            float dq0 = w1, dq1 = kk*v0, dq2 = kk*v1, dq3 = kk*v2;
            float* qc = g_qc + (size_t)bn * 4;
            float qw = qc[0], qx = qc[1], qy = qc[2], qz = qc[3];
            float nw = dq0*qw - (dq1*qx + dq2*qy + dq3*qz);
            float nx = dq0*qx + qw*dq1 + (dq2*qz - dq3*qy);
            float ny = dq0*qy + qw*dq2 + (dq3*qx - dq1*qz);
            float nz = dq0*qz + qw*dq3 + (dq1*qy - dq2*qx);
            qc[0]=nw; qc[1]=nx; qc[2]=ny; qc[3]=nz;
            float* xc = g_xc + (size_t)bn * FEAT;
            xc[0]=nw; xc[1]=nx; xc[2]=ny; xc[3]=nz;
            xc[4]=dq0; xc[5]=dq1; xc[6]=dq2; xc[7]=dq3;
            size_t od = ((size_t)b * PHs + step) * Nn + n;
            out[OFF_DQ  + od*4 + 0] = dq0; out[OFF_DQ + od*4 + 1] = dq1;
            out[OFF_DQ  + od*4 + 2] = dq2; out[OFF_DQ + od*4 + 3] = dq3;
            out[OFF_COV + od*6 + 0] = c0;  out[OFF_COV + od*6 + 1] = c1;
            out[OFF_COV + od*6 + 2] = c2;  out[OFF_COV + od*6 + 3] = c3;
            out[OFF_COV + od*6 + 4] = c4;  out[OFF_COV + od*6 + 5] = c5;
        }
    }
}

extern "C" void kernel_launch(void* const* d_in, const int* in_sizes, int n_in,
                              void* d_out, int out_size)
{
    const float* x    = (const float*)d_in[0];
    const float* h    = (const float*)d_in[1];
    const float* z    = (const float*)d_in[2];
    const float* q_t  = (const float*)d_in[3];
    const int*   T    = (const int*)  d_in[4];
    const float* W0   = (const float*)d_in[6];
    const float* b0p  = (const float*)d_in[7];
    const float* G0   = (const float*)d_in[8];
    const float* Wih  = (const float*)d_in[9];
    const float* Whh  = (const float*)d_in[10];
    const float* bih  = (const float*)d_in[11];
    const float* bhh  = (const float*)d_in[12];
    const float* Grnn = (const float*)d_in[13];
    const float* GA   = (const float*)d_in[14];
    const float* Wq   = (const float*)d_in[15];
    const float* bq   = (const float*)d_in[16];
    const float* Gq   = (const float*)d_in[17];
    const float* Wc   = (const float*)d_in[18];
    const float* bc   = (const float*)d_in[19];
    const float* Gc   = (const float*)d_in[20];
    const float* W3   = (const float*)d_in[21];
    const float* b3   = (const float*)d_in[22];
    const float* W6   = (const float*)d_in[23];
    const float* b6   = (const float*)d_in[24];
    float* out = (float*)d_out;

    const int SM_KTC = 4 * 128 * KSTR * 4;
    const int SM_KG  = KG_TOT * 4;
    static int attr_done = 0;
    if (!attr_done) {
        cudaFuncSetAttribute(ktc, cudaFuncAttributeMaxDynamicSharedMemorySize, SM_KTC);
        cudaFuncSetAttribute(kgates, cudaFuncAttributeMaxDynamicSharedMemorySize, SM_KG);
        attr_done = 1;
    }

    knorms<<<1, 128>>>(G0, Grnn, GA, Gq, Gc);
    kprep<<<(BN_*IN0_ + 255)/256, 256>>>(x, h, z, q_t, out);
    kroundw<<<(NW0 + NWIH + NWHH + 255)/256, 256>>>(W0, Wih, Whh);
    kbuildwqc<<<(NT_*256*HID_ + 255)/256, 256>>>(Wq, Wc, bq, bc);

    // tmp0 = xin(328) @ W0^T + b0
    ktc<<<dim3(2, HID_/128, Nn), 256, SM_KTC>>>(0, IN0_, 0, IN0_, HID_, IN0_, b0p, 0, T);
    kmix_rnnh<<<dim3(B_, HID_/64), 256>>>();

    // base = h_z(320) @ Wih_hz^T + bih  (asel=4: g_xin+FEAT, 8-block-aligned offset)
    ktc<<<dim3(2, G3_/128, Nn), 256, SM_KTC>>>(4, IN0_, 1, HZ_, G3_, HZ_, bih, 1, T);

    for (int t = 0; t < PHs; t++) {
        int cur = t & 1;
        ktc<<<dim3(2, G3_/128, Nn), 256, SM_KTC>>>(1 + cur, HID_, 2, HID_, G3_, HID_, bhh, 2, T);
        kgates<<<dim3(B_, HID_/64), 256, SM_KG>>>(Wih, T, cur);
        ktc<<<dim3(2, 2, Nn), 256, SM_KTC>>>(3, HID_, 3, HID_, 256, HID_, nullptr, 3, T);
        kheadmix<<<B_, 256>>>(W3, b3, W6, b6, T, out, t);
    }
}